// round 12
// baseline (speedup 1.0000x reference)
#include <cuda_runtime.h>
#include <cuda_fp16.h>

#define NN 256
#define SS 64
#define BB 1024
#define UNFOLDS 12
#define FAST_STEPS 11          // steps 0..10 sparse f16x2; step 11 dense fp32
#define TB 7                   // batches per CTA (147 CTAs cover 1024 with clamp)
#define GRID 147
#define NPAIR 128
#define NQUAD 64
#define NGRP 4                 // groups per CTA (split of the compacted slot list)
#define QPG (NQUAD / NGRP)     // dense quads per group (fp32 step)
#define CAP 192                // compacted-slot capacity per j (mask ~Bin(256,.5): 8 sigma)

// Scratch (device globals — no allocations allowed).
__device__ uint4  g_cpar[CAP * NN];        // [slot][j] {a2dup, b2dup, we2dup, wa2dup} f16x2
__device__ uchar4 g_cidx4[(CAP / 4) * NN]; // [slot/4][j] packed pre-neuron indices
__device__ int    g_cntmax;                // max active count over j
__device__ int    g_nblk;                  // 4-slot blocks per group (runtime)
__device__ float4 g_weq[NQUAD * NN];       // dense {hwe_i0..i3} f32 (colsums + fp32 step)
__device__ float4 g_abf[NPAIR * NN];       // dense {a_lo, a_hi, b_lo, b_hi} f32
__device__ float4 g_sparams[SS * NN];      // sensory {a, b, we, wsp} f32
__device__ float  g_sum_hw[NN];
__device__ float  g_sum_hwe[NN];
__device__ float  g_cmt[NN];
__device__ float  g_gl[NN];
__device__ float  g_gv[NN];

__device__ __forceinline__ float tanh_fast(float x) {
    float t;
    asm("tanh.approx.f32 %0, %1;" : "=f"(t) : "f"(x));
    return t;
}

__device__ __forceinline__ float softplus_f(float x) {
    return log1pf(expf(x));
}

// One compacted slot (one active pre-neuron i), covering batch-pairs (01,23,45,6x):
//   vv = v_hT[i] (one LDS.128 gather = 8 halves = all batches)
//   arg2 = a2dup * vpair + b2dup (HFMA2); t = tanh.f16x2 (2 batches per MUFU op)
//   num2[p] += we2dup * t ; den2[p] += wa2dup * t (f16 partials, folded every 4 slots)
__device__ __forceinline__ void proc_slot(const __half* vh, int ii, uint4 pq,
                                          unsigned* num2, unsigned* den2) {
    uint4 vv = *reinterpret_cast<const uint4*>(vh + ii * 8);
    unsigned a, t;
    asm("fma.rn.f16x2 %0, %1, %2, %3;" : "=r"(a) : "r"(pq.x), "r"(vv.x), "r"(pq.y));
    asm("tanh.approx.f16x2 %0, %1;" : "=r"(t) : "r"(a));
    asm("fma.rn.f16x2 %0, %1, %2, %0;" : "+r"(num2[0]) : "r"(pq.z), "r"(t));
    asm("fma.rn.f16x2 %0, %1, %2, %0;" : "+r"(den2[0]) : "r"(pq.w), "r"(t));
    asm("fma.rn.f16x2 %0, %1, %2, %3;" : "=r"(a) : "r"(pq.x), "r"(vv.y), "r"(pq.y));
    asm("tanh.approx.f16x2 %0, %1;" : "=r"(t) : "r"(a));
    asm("fma.rn.f16x2 %0, %1, %2, %0;" : "+r"(num2[1]) : "r"(pq.z), "r"(t));
    asm("fma.rn.f16x2 %0, %1, %2, %0;" : "+r"(den2[1]) : "r"(pq.w), "r"(t));
    asm("fma.rn.f16x2 %0, %1, %2, %3;" : "=r"(a) : "r"(pq.x), "r"(vv.z), "r"(pq.y));
    asm("tanh.approx.f16x2 %0, %1;" : "=r"(t) : "r"(a));
    asm("fma.rn.f16x2 %0, %1, %2, %0;" : "+r"(num2[2]) : "r"(pq.z), "r"(t));
    asm("fma.rn.f16x2 %0, %1, %2, %0;" : "+r"(den2[2]) : "r"(pq.w), "r"(t));
    asm("fma.rn.f16x2 %0, %1, %2, %3;" : "=r"(a) : "r"(pq.x), "r"(vv.w), "r"(pq.y));
    asm("tanh.approx.f16x2 %0, %1;" : "=r"(t) : "r"(a));
    asm("fma.rn.f16x2 %0, %1, %2, %0;" : "+r"(num2[3]) : "r"(pq.z), "r"(t));
    asm("fma.rn.f16x2 %0, %1, %2, %0;" : "+r"(den2[3]) : "r"(pq.w), "r"(t));
}

__device__ __forceinline__ void fold2(unsigned h2, float& alo, float& ahi) {
    float lo, hi;
    asm("{ .reg .b16 l, h;\n\t"
        "  mov.b32 {l, h}, %2;\n\t"
        "  cvt.f32.f16 %0, l;\n\t"
        "  cvt.f32.f16 %1, h; }"
        : "=f"(lo), "=f"(hi) : "r"(h2));
    alo += lo;
    ahi += hi;
}
__device__ __forceinline__ void fold_lo(unsigned h2, float& alo) {
    float lo;
    asm("{ .reg .b16 l, h;\n\t"
        "  mov.b32 {l, h}, %1;\n\t"
        "  cvt.f32.f16 %0, l; }"
        : "=f"(lo) : "r"(h2));
    alo += lo;
}

// ---------------------------------------------------------------------------
// Dense f32 tables (colsums + the fp32 closing step).
// ---------------------------------------------------------------------------
__global__ void k_prep(const float* __restrict__ w, const float* __restrict__ sigma,
                       const float* __restrict__ mu, const float* __restrict__ erev,
                       const float* __restrict__ mask) {
    int q = blockIdx.x, j = threadIdx.x;
    float a[4], b[4], e[4];
    #pragma unroll
    for (int k = 0; k < 4; k++) {
        int x = (4 * q + k) * NN + j;
        a[k] = 0.5f * sigma[x];
        b[k] = -a[k] * mu[x];
        e[k] = 0.5f * softplus_f(w[x]) * mask[x] * erev[x];
    }
    g_weq[q * NN + j] = make_float4(e[0], e[1], e[2], e[3]);
    g_abf[(2 * q)     * NN + j] = make_float4(a[0], a[1], b[0], b[1]);
    g_abf[(2 * q + 1) * NN + j] = make_float4(a[2], a[3], b[2], b[3]);
}

// Per-j compaction of active (mask!=0) pre-neurons; params dup-packed f16x2.
__global__ void k_compact(const float* __restrict__ w, const float* __restrict__ sigma,
                          const float* __restrict__ mu, const float* __restrict__ erev,
                          const float* __restrict__ mask) {
    int j = threadIdx.x;
    unsigned char idxbuf[CAP];
    int cnt = 0;
    for (int i = 0; i < NN; i++) {
        int x = i * NN + j;
        float m = mask[x];
        if (m != 0.f) {
            float a  = 0.5f * sigma[x];
            float b  = -a * mu[x];
            float hw = 0.5f * softplus_f(w[x]);          // mask=1 here
            float we = hw * erev[x];
            __half2 A = __half2half2(__float2half_rn(a));
            __half2 Bv = __half2half2(__float2half_rn(b));
            __half2 W = __half2half2(__float2half_rn(we));
            __half2 Wa = __half2half2(__float2half_rn(hw));
            uint4 pq;
            pq.x = *reinterpret_cast<unsigned*>(&A);
            pq.y = *reinterpret_cast<unsigned*>(&Bv);
            pq.z = *reinterpret_cast<unsigned*>(&W);
            pq.w = *reinterpret_cast<unsigned*>(&Wa);
            g_cpar[cnt * NN + j] = pq;
            idxbuf[cnt] = (unsigned char)i;
            cnt++;
        }
    }
    for (int s = cnt; s < CAP; s++) {
        g_cpar[s * NN + j] = make_uint4(0u, 0u, 0u, 0u);  // contributes exactly 0
        idxbuf[s] = 0;
    }
    for (int bq = 0; bq < CAP / 4; bq++)
        g_cidx4[bq * NN + j] = make_uchar4(idxbuf[4 * bq], idxbuf[4 * bq + 1],
                                           idxbuf[4 * bq + 2], idxbuf[4 * bq + 3]);
    atomicMax(&g_cntmax, cnt);
}

__global__ void k_final() {
    int c = g_cntmax;
    int nb = (c + NGRP * 4 - 1) / (NGRP * 4);   // 4-slot blocks per group
    if (nb < 1) nb = 1;
    if (nb > CAP / (NGRP * 4)) nb = CAP / (NGRP * 4);
    g_nblk = nb;
}

__global__ void k_sprep(const float* __restrict__ sw, const float* __restrict__ ssig,
                        const float* __restrict__ smu, const float* __restrict__ serev,
                        const float* __restrict__ smask) {
    int s = blockIdx.x, j = threadIdx.x;
    int idx = s * NN + j;
    float wsp = softplus_f(sw[idx]) * smask[idx];
    float a   = 0.5f * ssig[idx];
    g_sparams[idx] = make_float4(a, -a * smu[idx], wsp * serev[idx], wsp);
}

__global__ void k_colsums(const float* __restrict__ gleak, const float* __restrict__ vleak,
                          const float* __restrict__ cm) {
    int j = threadIdx.x;
    float shw = 0.f, shwe = 0.f;
    #pragma unroll 8
    for (int q = 0; q < NQUAD; q++) {
        float4 e = g_weq[q * NN + j];
        shwe += (e.x + e.y) + (e.z + e.w);
        shw  += (fabsf(e.x) + fabsf(e.y)) + (fabsf(e.z) + fabsf(e.w));
    }
    g_sum_hw[j]  = shw;
    g_sum_hwe[j] = shwe;
    float gl = softplus_f(gleak[j]);
    g_gl[j]  = gl;
    g_gv[j]  = gl * vleak[j];
    g_cmt[j] = softplus_f(cm[j]) * (float)UNFOLDS;
}

// SMEM layout (dynamic)
#define SM_VF   0
#define SM_VHT  (TB * NN * 4)                    // 7168
#define SM_XIN  (SM_VHT + NN * 8 * 2)            // 11264
#define SM_PART (SM_XIN + TB * SS * 4)           // 13056
#define SM_TOTAL (SM_PART + NGRP * TB * NN * 8)  // 70400

// ---------------------------------------------------------------------------
// Main: 147 CTAs x 1024 threads = 4 groups of 256 j-threads.
// Fast steps: group ig processes compacted slots [ig*4*nblk, (ig+1)*4*nblk)
// for ALL 7 batches via transposed v gathers (batch-paired f16x2 tanh).
// Final step: dense fp32 over i in [ig*64, ig*64+64).
// Partials merged via 4-slot SMEM buffer; group ig owns batches 2*ig..(+1).
// ---------------------------------------------------------------------------
__global__ void __launch_bounds__(1024, 1) k_main(const float* __restrict__ inputs,
                                                  const float* __restrict__ state,
                                                  float* __restrict__ out) {
    extern __shared__ char smem[];
    float  (*v_f)[NN]      = reinterpret_cast<float (*)[NN]>(smem + SM_VF);
    __half* v_hT           = reinterpret_cast<__half*>(smem + SM_VHT);   // [NN][8]
    float  (*xin)[SS]      = reinterpret_cast<float (*)[SS]>(smem + SM_XIN);
    float2 (*part)[TB][NN] = reinterpret_cast<float2 (*)[TB][NN]>(smem + SM_PART);

    int tid = threadIdx.x;
    int ig  = tid >> 8;          // 0..3
    int j   = tid & 255;
    int b0  = blockIdx.x * TB;
    int ob      = ig * 2;
    int own_cnt = (ig == 3) ? 1 : 2;

    if (tid < TB * SS) xin[tid >> 6][tid & 63] = inputs[min(b0 * SS + tid, BB * SS - 1)];
    for (int idx = tid; idx < TB * NN; idx += 1024) {
        float v = state[min(b0 * NN + idx, BB * NN - 1)];
        int bb = idx >> 8, jj = idx & 255;
        v_f[bb][jj] = v;
        v_hT[jj * 8 + bb] = __float2half_rn(v);
    }
    if (tid < NN) v_hT[tid * 8 + 7] = __float2half_rn(0.f);   // pad batch
    __syncthreads();

    // --- sensory pass (step-invariant) for owned batches (<=2) ---
    float ncr[2], dcr[2];
    {
        float sn[2] = {0.f, 0.f}, sd[2] = {0.f, 0.f};
        #pragma unroll 2
        for (int s = 0; s < SS; s++) {
            float4 q = g_sparams[s * NN + j];
            #pragma unroll
            for (int k = 0; k < 2; k++) {
                int bx = ob + min(k, own_cnt - 1);
                float t  = tanh_fast(fmaf(q.x, xin[bx][s], q.y));
                float sg = fmaf(0.5f, t, 0.5f);
                sn[k] = fmaf(q.z, sg, sn[k]);
                sd[k] = fmaf(q.w, sg, sd[k]);
            }
        }
        float gv = g_gv[j], she = g_sum_hwe[j], gl = g_gl[j], shw = g_sum_hw[j];
        float cmt0 = g_cmt[j];
        #pragma unroll
        for (int k = 0; k < 2; k++) {
            ncr[k] = gv + she + sn[k];
            dcr[k] = cmt0 + gl + shw + sd[k] + 1e-8f;
        }
    }
    float cmt = g_cmt[j];
    int nblk = g_nblk;                      // uniform runtime bound
    int sbase = ig * 4 * nblk;              // this group's first slot

    const int ibase = ig * (NN / NGRP);
    const float4* WEQ = g_weq + (ig * QPG) * NN + j;
    const float4* ABF = g_abf + (ig * (NPAIR / NGRP)) * NN + j;

    for (int step = 0; step < UNFOLDS; step++) {
        float numf[TB], denf[TB];
        #pragma unroll
        for (int b = 0; b < TB; b++) { numf[b] = 0.f; denf[b] = 0.f; }

        if (step < FAST_STEPS) {
            // ---------- sparse f16x2 path over compacted slots ----------
            for (int blk = 0; blk < nblk; blk++) {
                int s0 = sbase + blk * 4;
                uchar4 ii = g_cidx4[(s0 >> 2) * NN + j];
                unsigned num2[4] = {0u, 0u, 0u, 0u};
                unsigned den2[4] = {0u, 0u, 0u, 0u};
                uint4 p0 = g_cpar[(s0    ) * NN + j];
                uint4 p1 = g_cpar[(s0 + 1) * NN + j];
                proc_slot(v_hT, ii.x, p0, num2, den2);
                proc_slot(v_hT, ii.y, p1, num2, den2);
                uint4 p2 = g_cpar[(s0 + 2) * NN + j];
                uint4 p3 = g_cpar[(s0 + 3) * NN + j];
                proc_slot(v_hT, ii.z, p2, num2, den2);
                proc_slot(v_hT, ii.w, p3, num2, den2);
                // fold 4-slot f16 partials to f32 (batch 7 = pad, hi of pair 3 dropped)
                fold2(num2[0], numf[0], numf[1]);
                fold2(num2[1], numf[2], numf[3]);
                fold2(num2[2], numf[4], numf[5]);
                fold_lo(num2[3], numf[6]);
                fold2(den2[0], denf[0], denf[1]);
                fold2(den2[1], denf[2], denf[3]);
                fold2(den2[2], denf[4], denf[5]);
                fold_lo(den2[3], denf[6]);
            }
        } else {
            // ---------- accurate dense fp32 path (last step) ----------
            #pragma unroll 2
            for (int q = 0; q < QPG; q++) {
                float4 a0 = ABF[(q * 2) * NN];
                float4 a1 = ABF[(q * 2 + 1) * NN];
                float4 e  = WEQ[q * NN];
                #pragma unroll
                for (int b = 0; b < TB; b++) {
                    float4 v = *reinterpret_cast<const float4*>(&v_f[b][ibase + q * 4]);
                    float t0 = tanh_fast(fmaf(a0.x, v.x, a0.z));
                    float t1 = tanh_fast(fmaf(a0.y, v.y, a0.w));
                    float t2 = tanh_fast(fmaf(a1.x, v.z, a1.z));
                    float t3 = tanh_fast(fmaf(a1.y, v.w, a1.w));
                    numf[b] = fmaf(e.x, t0, numf[b]); denf[b] = fmaf(fabsf(e.x), t0, denf[b]);
                    numf[b] = fmaf(e.y, t1, numf[b]); denf[b] = fmaf(fabsf(e.y), t1, denf[b]);
                    numf[b] = fmaf(e.z, t2, numf[b]); denf[b] = fmaf(fabsf(e.z), t2, denf[b]);
                    numf[b] = fmaf(e.w, t3, numf[b]); denf[b] = fmaf(fabsf(e.w), t3, denf[b]);
                }
            }
        }

        #pragma unroll
        for (int b = 0; b < TB; b++)
            part[ig][b][j] = make_float2(numf[b], denf[b]);
        __syncthreads();

        #pragma unroll
        for (int k = 0; k < 2; k++) {
            if (k < own_cnt) {
                int b = ob + k;
                float2 p0 = part[0][b][j];
                float2 p1 = part[1][b][j];
                float2 p2 = part[2][b][j];
                float2 p3 = part[3][b][j];
                float n = (p0.x + p1.x) + (p2.x + p3.x);
                float d = (p0.y + p1.y) + (p2.y + p3.y);
                float vn = (fmaf(cmt, v_f[b][j], ncr[k]) + n) / (d + dcr[k]);
                v_f[b][j] = vn;
                v_hT[j * 8 + b] = __float2half_rn(vn);
            }
        }
        __syncthreads();
    }

    #pragma unroll
    for (int k = 0; k < 2; k++) {
        if (k < own_cnt) {
            int b = ob + k;
            if (b0 + b < BB) out[(b0 + b) * NN + j] = v_f[b][j];
        }
    }
}

extern "C" void kernel_launch(void* const* d_in, const int* in_sizes, int n_in,
                              void* d_out, int out_size) {
    const float* inputs = (const float*)d_in[0];
    const float* state  = (const float*)d_in[1];
    const float* gleak  = (const float*)d_in[2];
    const float* vleak  = (const float*)d_in[3];
    const float* cm     = (const float*)d_in[4];
    const float* w      = (const float*)d_in[5];
    const float* sigma  = (const float*)d_in[6];
    const float* mu     = (const float*)d_in[7];
    const float* erev   = (const float*)d_in[8];
    const float* sw     = (const float*)d_in[9];
    const float* ssig   = (const float*)d_in[10];
    const float* smu    = (const float*)d_in[11];
    const float* serev  = (const float*)d_in[12];
    const float* mask   = (const float*)d_in[13];
    const float* smask  = (const float*)d_in[14];
    float* out = (float*)d_out;

    cudaFuncSetAttribute(k_main, cudaFuncAttributeMaxDynamicSharedMemorySize, SM_TOTAL);

    k_prep   <<<NQUAD, NN>>>(w, sigma, mu, erev, mask);
    k_compact<<<1, NN>>>(w, sigma, mu, erev, mask);
    k_final  <<<1, 1>>>();
    k_sprep  <<<SS, NN>>>(sw, ssig, smu, serev, smask);
    k_colsums<<<1,  NN>>>(gleak, vleak, cm);
    k_main   <<<GRID, 1024, SM_TOTAL>>>(inputs, state, out);
}

// round 13
// speedup vs baseline: 1.3608x; 1.3608x over previous
#include <cuda_runtime.h>
#include <cuda_fp16.h>

#define NN 256
#define SS 64
#define BB 1024
#define UNFOLDS 12
#define FAST_STEPS 11          // steps 0..10 sparse f16x2; step 11 dense fp32
#define TB 7                   // batches per CTA (147 CTAs cover 1024 with clamp)
#define GRID 147
#define NPAIR 128
#define NQUAD 64
#define NGRP 4                 // groups per CTA
#define QPG (NQUAD / NGRP)     // dense quads per group (fp32 step)
#define CAP 192                // compacted-slot capacity per j

// Scratch (device globals — no allocations allowed).
__device__ uint4  g_cpar[CAP * NN];         // [slot][j] {a2dup, b2dup, we2dup, wa2dup} f16x2
__device__ unsigned char g_cidxT[NN * CAP]; // [j][slot] pre-neuron index
__device__ int    g_cntmax;                 // max active count over j
__device__ int    g_nblk;                   // 2-slot blocks per group (runtime)
__device__ float4 g_weq[NQUAD * NN];        // dense {hwe_i0..i3} f32 (colsums + fp32 step)
__device__ float4 g_abf[NPAIR * NN];        // dense {a_lo, a_hi, b_lo, b_hi} f32
__device__ float4 g_sparams[SS * NN];       // sensory {a, b, we, wsp} f32
__device__ float  g_sum_hw[NN];
__device__ float  g_sum_hwe[NN];
__device__ float  g_cmt[NN];
__device__ float  g_gl[NN];
__device__ float  g_gv[NN];

__device__ __forceinline__ float tanh_fast(float x) {
    float t;
    asm("tanh.approx.f32 %0, %1;" : "=f"(t) : "f"(x));
    return t;
}

__device__ __forceinline__ float softplus_f(float x) {
    return log1pf(expf(x));
}

// One compacted slot (one active pre-neuron i), batch-pairs (01,23,45,6pad):
//   vv = v_hT[i] (one LDS.128 gather = all batches)
//   arg2 = a2dup*vpair + b2dup (HFMA2); t = tanh.f16x2 (2 batches per XU op)
//   num2[p] += we2dup*t ; den2[p] += wa2dup*t (f16 partials, folded every 4 slots)
__device__ __forceinline__ void proc_slot2(uint4 vv, uint4 pq,
                                           unsigned* num2, unsigned* den2) {
    unsigned a, t;
    asm("fma.rn.f16x2 %0, %1, %2, %3;" : "=r"(a) : "r"(pq.x), "r"(vv.x), "r"(pq.y));
    asm("tanh.approx.f16x2 %0, %1;" : "=r"(t) : "r"(a));
    asm("fma.rn.f16x2 %0, %1, %2, %0;" : "+r"(num2[0]) : "r"(pq.z), "r"(t));
    asm("fma.rn.f16x2 %0, %1, %2, %0;" : "+r"(den2[0]) : "r"(pq.w), "r"(t));
    asm("fma.rn.f16x2 %0, %1, %2, %3;" : "=r"(a) : "r"(pq.x), "r"(vv.y), "r"(pq.y));
    asm("tanh.approx.f16x2 %0, %1;" : "=r"(t) : "r"(a));
    asm("fma.rn.f16x2 %0, %1, %2, %0;" : "+r"(num2[1]) : "r"(pq.z), "r"(t));
    asm("fma.rn.f16x2 %0, %1, %2, %0;" : "+r"(den2[1]) : "r"(pq.w), "r"(t));
    asm("fma.rn.f16x2 %0, %1, %2, %3;" : "=r"(a) : "r"(pq.x), "r"(vv.z), "r"(pq.y));
    asm("tanh.approx.f16x2 %0, %1;" : "=r"(t) : "r"(a));
    asm("fma.rn.f16x2 %0, %1, %2, %0;" : "+r"(num2[2]) : "r"(pq.z), "r"(t));
    asm("fma.rn.f16x2 %0, %1, %2, %0;" : "+r"(den2[2]) : "r"(pq.w), "r"(t));
    asm("fma.rn.f16x2 %0, %1, %2, %3;" : "=r"(a) : "r"(pq.x), "r"(vv.w), "r"(pq.y));
    asm("tanh.approx.f16x2 %0, %1;" : "=r"(t) : "r"(a));
    asm("fma.rn.f16x2 %0, %1, %2, %0;" : "+r"(num2[3]) : "r"(pq.z), "r"(t));
    asm("fma.rn.f16x2 %0, %1, %2, %0;" : "+r"(den2[3]) : "r"(pq.w), "r"(t));
}

__device__ __forceinline__ void fold2(unsigned h2, float& alo, float& ahi) {
    float lo, hi;
    asm("{ .reg .b16 l, h;\n\t"
        "  mov.b32 {l, h}, %2;\n\t"
        "  cvt.f32.f16 %0, l;\n\t"
        "  cvt.f32.f16 %1, h; }"
        : "=f"(lo), "=f"(hi) : "r"(h2));
    alo += lo;
    ahi += hi;
}
__device__ __forceinline__ void fold_lo(unsigned h2, float& alo) {
    float lo;
    asm("{ .reg .b16 l, h;\n\t"
        "  mov.b32 {l, h}, %1;\n\t"
        "  cvt.f32.f16 %0, l; }"
        : "=f"(lo) : "r"(h2));
    alo += lo;
}

// ---------------------------------------------------------------------------
// Dense f32 tables (colsums + the fp32 closing step).
// ---------------------------------------------------------------------------
__global__ void k_prep(const float* __restrict__ w, const float* __restrict__ sigma,
                       const float* __restrict__ mu, const float* __restrict__ erev,
                       const float* __restrict__ mask) {
    int q = blockIdx.x, j = threadIdx.x;
    float a[4], b[4], e[4];
    #pragma unroll
    for (int k = 0; k < 4; k++) {
        int x = (4 * q + k) * NN + j;
        a[k] = 0.5f * sigma[x];
        b[k] = -a[k] * mu[x];
        e[k] = 0.5f * softplus_f(w[x]) * mask[x] * erev[x];
    }
    g_weq[q * NN + j] = make_float4(e[0], e[1], e[2], e[3]);
    g_abf[(2 * q)     * NN + j] = make_float4(a[0], a[1], b[0], b[1]);
    g_abf[(2 * q + 1) * NN + j] = make_float4(a[2], a[3], b[2], b[3]);
}

// Parallel per-j compaction: one block per j, ballot + warp-prefix (no local mem).
__global__ void k_compact(const float* __restrict__ w, const float* __restrict__ sigma,
                          const float* __restrict__ mu, const float* __restrict__ erev,
                          const float* __restrict__ mask) {
    int j = blockIdx.x, i = threadIdx.x;
    int lane = i & 31, wid = i >> 5;
    int x = i * NN + j;
    bool act = (mask[x] != 0.f);
    unsigned bal = __ballot_sync(0xFFFFFFFFu, act);
    int rank = __popc(bal & ((1u << lane) - 1u));
    __shared__ int woff[9];
    if (lane == 0) woff[wid + 1] = __popc(bal);
    __syncthreads();
    if (i == 0) {
        woff[0] = 0;
        for (int k = 1; k <= 8; k++) woff[k] += woff[k - 1];
        atomicMax(&g_cntmax, woff[8]);
    }
    __syncthreads();
    int cnt = woff[8];
    if (act) {
        int slot = woff[wid] + rank;
        float a  = 0.5f * sigma[x];
        float b  = -a * mu[x];
        float hw = 0.5f * softplus_f(w[x]);        // mask=1 here
        float we = hw * erev[x];
        __half2 A  = __half2half2(__float2half_rn(a));
        __half2 Bv = __half2half2(__float2half_rn(b));
        __half2 W  = __half2half2(__float2half_rn(we));
        __half2 Wa = __half2half2(__float2half_rn(hw));
        uint4 pq;
        pq.x = *reinterpret_cast<unsigned*>(&A);
        pq.y = *reinterpret_cast<unsigned*>(&Bv);
        pq.z = *reinterpret_cast<unsigned*>(&W);
        pq.w = *reinterpret_cast<unsigned*>(&Wa);
        g_cpar[slot * NN + j] = pq;
        g_cidxT[j * CAP + slot] = (unsigned char)i;
    }
    // zero-pad remaining slots (contribute exactly 0)
    for (int s = cnt + i; s < CAP; s += NN) {
        g_cpar[s * NN + j] = make_uint4(0u, 0u, 0u, 0u);
        g_cidxT[j * CAP + s] = 0;
    }
}

__global__ void k_final() {
    int c = g_cntmax;
    int nb = (c + NGRP * 2 - 1) / (NGRP * 2);   // 2-slot blocks per group
    if (nb < 1) nb = 1;
    if (nb > CAP / (NGRP * 2)) nb = CAP / (NGRP * 2);
    g_nblk = nb;
}

__global__ void k_sprep(const float* __restrict__ sw, const float* __restrict__ ssig,
                        const float* __restrict__ smu, const float* __restrict__ serev,
                        const float* __restrict__ smask) {
    int s = blockIdx.x, j = threadIdx.x;
    int idx = s * NN + j;
    float wsp = softplus_f(sw[idx]) * smask[idx];
    float a   = 0.5f * ssig[idx];
    g_sparams[idx] = make_float4(a, -a * smu[idx], wsp * serev[idx], wsp);
}

__global__ void k_colsums(const float* __restrict__ gleak, const float* __restrict__ vleak,
                          const float* __restrict__ cm) {
    int j = threadIdx.x;
    float shw = 0.f, shwe = 0.f;
    #pragma unroll 8
    for (int q = 0; q < NQUAD; q++) {
        float4 e = g_weq[q * NN + j];
        shwe += (e.x + e.y) + (e.z + e.w);
        shw  += (fabsf(e.x) + fabsf(e.y)) + (fabsf(e.z) + fabsf(e.w));
    }
    g_sum_hw[j]  = shw;
    g_sum_hwe[j] = shwe;
    float gl = softplus_f(gleak[j]);
    g_gl[j]  = gl;
    g_gv[j]  = gl * vleak[j];
    g_cmt[j] = softplus_f(cm[j]) * (float)UNFOLDS;
}

// SMEM layout (dynamic)
#define SM_VF   0
#define SM_VHT  (TB * NN * 4)                    // 7168
#define SM_XIN  (SM_VHT + NN * 8 * 2)            // 11264
#define SM_PART (SM_XIN + TB * SS * 4)           // 13056
#define SM_TOTAL (SM_PART + NGRP * TB * NN * 8)  // 70400

// ---------------------------------------------------------------------------
// Main: 147 CTAs x 1024 threads = 4 groups of 256 j-threads.
// Fast steps: group ig processes compacted slots [ig*2*nblk, (ig+1)*2*nblk)
// for ALL 7 batches via transposed v gathers (batch-paired f16x2 tanh).
// Final step: dense fp32 over i in [ig*64, ig*64+64).
// ---------------------------------------------------------------------------
__global__ void __launch_bounds__(1024, 1) k_main(const float* __restrict__ inputs,
                                                  const float* __restrict__ state,
                                                  float* __restrict__ out) {
    extern __shared__ char smem[];
    float  (*v_f)[NN]      = reinterpret_cast<float (*)[NN]>(smem + SM_VF);
    __half* v_hT           = reinterpret_cast<__half*>(smem + SM_VHT);   // [NN][8]
    float  (*xin)[SS]      = reinterpret_cast<float (*)[SS]>(smem + SM_XIN);
    float2 (*part)[TB][NN] = reinterpret_cast<float2 (*)[TB][NN]>(smem + SM_PART);

    int tid = threadIdx.x;
    int ig  = tid >> 8;          // 0..3
    int j   = tid & 255;
    int b0  = blockIdx.x * TB;
    int ob      = ig * 2;
    int own_cnt = (ig == 3) ? 1 : 2;

    if (tid < TB * SS) xin[tid >> 6][tid & 63] = inputs[min(b0 * SS + tid, BB * SS - 1)];
    for (int idx = tid; idx < TB * NN; idx += 1024) {
        float v = state[min(b0 * NN + idx, BB * NN - 1)];
        int bb = idx >> 8, jj = idx & 255;
        v_f[bb][jj] = v;
        v_hT[jj * 8 + bb] = __float2half_rn(v);
    }
    if (tid < NN) v_hT[tid * 8 + 7] = __float2half_rn(0.f);   // pad batch
    __syncthreads();

    // --- sensory pass (step-invariant) for owned batches (<=2) ---
    float ncr[2], dcr[2];
    {
        float sn[2] = {0.f, 0.f}, sd[2] = {0.f, 0.f};
        #pragma unroll 2
        for (int s = 0; s < SS; s++) {
            float4 q = g_sparams[s * NN + j];
            #pragma unroll
            for (int k = 0; k < 2; k++) {
                int bx = ob + min(k, own_cnt - 1);
                float t  = tanh_fast(fmaf(q.x, xin[bx][s], q.y));
                float sg = fmaf(0.5f, t, 0.5f);
                sn[k] = fmaf(q.z, sg, sn[k]);
                sd[k] = fmaf(q.w, sg, sd[k]);
            }
        }
        float gv = g_gv[j], she = g_sum_hwe[j], gl = g_gl[j], shw = g_sum_hw[j];
        float cmt0 = g_cmt[j];
        #pragma unroll
        for (int k = 0; k < 2; k++) {
            ncr[k] = gv + she + sn[k];
            dcr[k] = cmt0 + gl + shw + sd[k] + 1e-8f;
        }
    }
    float cmt = g_cmt[j];
    int nblk = g_nblk;                        // uniform runtime bound
    int sbase = ig * 2 * nblk;                // this group's first slot
    const unsigned char* CI = g_cidxT + j * CAP;

    const int ibase = ig * (NN / NGRP);
    const float4* WEQ = g_weq + (ig * QPG) * NN + j;
    const float4* ABF = g_abf + (ig * (NPAIR / NGRP)) * NN + j;

    for (int step = 0; step < UNFOLDS; step++) {
        float numf[TB], denf[TB];
        #pragma unroll
        for (int b = 0; b < TB; b++) { numf[b] = 0.f; denf[b] = 0.f; }

        if (step < FAST_STEPS) {
            // ---------- sparse f16x2 path over compacted slots ----------
            unsigned num2[4] = {0u, 0u, 0u, 0u};
            unsigned den2[4] = {0u, 0u, 0u, 0u};
            for (int blk = 0; blk < nblk; blk++) {
                int s0 = sbase + blk * 2;
                uchar2 ii = *reinterpret_cast<const uchar2*>(CI + s0);
                uint4 p0 = g_cpar[(s0    ) * NN + j];
                uint4 p1 = g_cpar[(s0 + 1) * NN + j];
                uint4 v0 = *reinterpret_cast<const uint4*>(v_hT + (int)ii.x * 8);
                uint4 v1 = *reinterpret_cast<const uint4*>(v_hT + (int)ii.y * 8);
                proc_slot2(v0, p0, num2, den2);
                proc_slot2(v1, p1, num2, den2);
                if ((blk & 1) || (blk == nblk - 1)) {
                    // fold 4-slot f16 partials to f32 (batch 7 = pad dropped)
                    fold2(num2[0], numf[0], numf[1]);
                    fold2(num2[1], numf[2], numf[3]);
                    fold2(num2[2], numf[4], numf[5]);
                    fold_lo(num2[3], numf[6]);
                    fold2(den2[0], denf[0], denf[1]);
                    fold2(den2[1], denf[2], denf[3]);
                    fold2(den2[2], denf[4], denf[5]);
                    fold_lo(den2[3], denf[6]);
                    #pragma unroll
                    for (int p = 0; p < 4; p++) { num2[p] = 0u; den2[p] = 0u; }
                }
            }
        } else {
            // ---------- accurate dense fp32 path (last step) ----------
            #pragma unroll 2
            for (int q = 0; q < QPG; q++) {
                float4 a0 = ABF[(q * 2) * NN];
                float4 a1 = ABF[(q * 2 + 1) * NN];
                float4 e  = WEQ[q * NN];
                #pragma unroll
                for (int b = 0; b < TB; b++) {
                    float4 v = *reinterpret_cast<const float4*>(&v_f[b][ibase + q * 4]);
                    float t0 = tanh_fast(fmaf(a0.x, v.x, a0.z));
                    float t1 = tanh_fast(fmaf(a0.y, v.y, a0.w));
                    float t2 = tanh_fast(fmaf(a1.x, v.z, a1.z));
                    float t3 = tanh_fast(fmaf(a1.y, v.w, a1.w));
                    numf[b] = fmaf(e.x, t0, numf[b]); denf[b] = fmaf(fabsf(e.x), t0, denf[b]);
                    numf[b] = fmaf(e.y, t1, numf[b]); denf[b] = fmaf(fabsf(e.y), t1, denf[b]);
                    numf[b] = fmaf(e.z, t2, numf[b]); denf[b] = fmaf(fabsf(e.z), t2, denf[b]);
                    numf[b] = fmaf(e.w, t3, numf[b]); denf[b] = fmaf(fabsf(e.w), t3, denf[b]);
                }
            }
        }

        #pragma unroll
        for (int b = 0; b < TB; b++)
            part[ig][b][j] = make_float2(numf[b], denf[b]);
        __syncthreads();

        #pragma unroll
        for (int k = 0; k < 2; k++) {
            if (k < own_cnt) {
                int b = ob + k;
                float2 p0 = part[0][b][j];
                float2 p1 = part[1][b][j];
                float2 p2 = part[2][b][j];
                float2 p3 = part[3][b][j];
                float n = (p0.x + p1.x) + (p2.x + p3.x);
                float d = (p0.y + p1.y) + (p2.y + p3.y);
                float vn = (fmaf(cmt, v_f[b][j], ncr[k]) + n) / (d + dcr[k]);
                v_f[b][j] = vn;
                v_hT[j * 8 + b] = __float2half_rn(vn);
            }
        }
        __syncthreads();
    }

    #pragma unroll
    for (int k = 0; k < 2; k++) {
        if (k < own_cnt) {
            int b = ob + k;
            if (b0 + b < BB) out[(b0 + b) * NN + j] = v_f[b][j];
        }
    }
}

extern "C" void kernel_launch(void* const* d_in, const int* in_sizes, int n_in,
                              void* d_out, int out_size) {
    const float* inputs = (const float*)d_in[0];
    const float* state  = (const float*)d_in[1];
    const float* gleak  = (const float*)d_in[2];
    const float* vleak  = (const float*)d_in[3];
    const float* cm     = (const float*)d_in[4];
    const float* w      = (const float*)d_in[5];
    const float* sigma  = (const float*)d_in[6];
    const float* mu     = (const float*)d_in[7];
    const float* erev   = (const float*)d_in[8];
    const float* sw     = (const float*)d_in[9];
    const float* ssig   = (const float*)d_in[10];
    const float* smu    = (const float*)d_in[11];
    const float* serev  = (const float*)d_in[12];
    const float* mask   = (const float*)d_in[13];
    const float* smask  = (const float*)d_in[14];
    float* out = (float*)d_out;

    cudaFuncSetAttribute(k_main, cudaFuncAttributeMaxDynamicSharedMemorySize, SM_TOTAL);

    k_prep   <<<NQUAD, NN>>>(w, sigma, mu, erev, mask);
    k_compact<<<NN, NN>>>(w, sigma, mu, erev, mask);
    k_final  <<<1, 1>>>();
    k_sprep  <<<SS, NN>>>(sw, ssig, smu, serev, smask);
    k_colsums<<<1,  NN>>>(gleak, vleak, cm);
    k_main   <<<GRID, 1024, SM_TOTAL>>>(inputs, state, out);
}